// round 12
// baseline (speedup 1.0000x reference)
#include <cuda_runtime.h>
#include <math.h>

typedef unsigned long long u64;

#define NMAX 20000
#define EMAX 320000
#define N32  (NMAX * 32)

// f32x2 packed helpers
#define FMA2(d, a, b, c) asm("fma.rn.f32x2 %0, %1, %2, %3;" : "=l"(d) : "l"(a), "l"(b), "l"(c))
#define MUL2(d, a, b)    asm("mul.rn.f32x2 %0, %1, %2;" : "=l"(d) : "l"(a), "l"(b))
#define PACK2(d, lo, hi) asm("mov.b64 %0, {%1, %2};" : "=l"(d) : "f"(lo), "f"(hi))
#define UNPACK2(lo, hi, s) asm("mov.b64 {%0, %1}, %2;" : "=f"(lo), "=f"(hi) : "l"(s))

// split a float4 into two packed f32x2 (register renaming, no SASS cost)
#define SPLIT4(lo, hi, v4) { lo = *(const u64*)&(v4).x; hi = *(const u64*)&(v4).z; }

__device__ __forceinline__ float hadd2(u64 v) {
    float lo, hi; UNPACK2(lo, hi, v); return lo + hi;
}

// CSR build scratch
__device__ int g_deg[NMAX];
__device__ int g_off[NMAX + 1];
__device__ int g_cur[NMAX];
__device__ int g_edge[EMAX];

// per-edge precomputed data: {h0,h1,h2,rb0},{rb1,rb2,rb3,rb4},{rb5,rb6,rb7,pad}
__device__ float4 g_edata[EMAX * 3];

// transposed node features (plane-major for coalesced gather)
__device__ float g_n1T[3][N32];
__device__ float g_n2T[9][N32];

// aggregated per-node accumulators (plane-major)
__device__ float g_A0[N32];
__device__ float g_A1[3][N32];
__device__ float g_A2[9][N32];

// ---------------------------------------------------------------------------
// fused histogram + feature transpose
__global__ void hist_transpose_kernel(const int* __restrict__ idx_i,
                                      const float* __restrict__ node1,
                                      const float* __restrict__ node2,
                                      int E, int NC) {
    int i = blockIdx.x * blockDim.x + threadIdx.x;
    if (i < E) atomicAdd(&g_deg[idx_i[i]], 1);
    if (i < NC) {
#pragma unroll
        for (int a = 0; a < 3; a++) g_n1T[a][i] = node1[(size_t)i * 3 + a];
#pragma unroll
        for (int k = 0; k < 9; k++) g_n2T[k][i] = node2[(size_t)i * 9 + k];
    }
}

__global__ void scan_kernel(int N, int E) {
    __shared__ int ssum[1024];
    int t = threadIdx.x;
    int chunk = (N + 1023) / 1024;
    int base = t * chunk;
    int s = 0;
    for (int k = 0; k < chunk; k++) {
        int idx = base + k;
        if (idx < N) s += g_deg[idx];
    }
    ssum[t] = s;
    __syncthreads();
    for (int off = 1; off < 1024; off <<= 1) {
        int v = (t >= off) ? ssum[t - off] : 0;
        __syncthreads();
        ssum[t] += v;
        __syncthreads();
    }
    int run = ssum[t] - s;
    for (int k = 0; k < chunk; k++) {
        int idx = base + k;
        if (idx < N) {
            int d = g_deg[idx];
            g_off[idx] = run;
            g_cur[idx] = run;
            run += d;
        }
    }
    if (t == 0) g_off[N] = E;
}

// fused CSR scatter + per-edge geometry/rbf precompute
__global__ void scatter_pre_kernel(const int* __restrict__ idx_i,
                                   const float* __restrict__ rij,
                                   int E) {
    int e = blockIdx.x * blockDim.x + threadIdx.x;
    if (e >= E) return;

    int p = atomicAdd(&g_cur[idx_i[e]], 1);
    g_edge[p] = e;

    float rx = rij[3 * e + 0];
    float ry = rij[3 * e + 1];
    float rz = rij[3 * e + 2];
    float dd = rx * rx + ry * ry + rz * rz + 1e-12f;
    float iv = rsqrtf(dd);
    float dist = dd * iv;
    float h0 = rx * iv, h1 = ry * iv, h2 = rz * iv;

    float uu = fminf(dist * 0.2f, 1.0f);
    float fc = 0.5f * (__cosf(3.14159265358979323846f * uu) + 1.0f);

    float rb[8];
#pragma unroll
    for (int b = 0; b < 8; b++) {
        float cb = 0.5f + (float)b * (4.5f / 7.0f);
        float dl = dist - cb;
        rb[b] = __expf(-4.0f * dl * dl) * fc;
    }

    g_edata[e * 3 + 0] = make_float4(h0, h1, h2, rb[0]);
    g_edata[e * 3 + 1] = make_float4(rb[1], rb[2], rb[3], rb[4]);
    g_edata[e * 3 + 2] = make_float4(rb[5], rb[6], rb[7], 0.0f);
}

// ---------------------------------------------------------------------------
// Edge aggregation: persistent warps, grid-stride over nodes; lane = channel.
// (Byte-identical to the measured R10/R11 version.)
// ---------------------------------------------------------------------------
__global__ __launch_bounds__(128, 3)
void edge_kernel(const float* __restrict__ node0,
                 const float* __restrict__ Wrad,
                 const int* __restrict__ idx_j,
                 int N)
{
    int warp = threadIdx.x >> 5;
    int lane = threadIdx.x & 31;
    int gwarp = blockIdx.x * 4 + warp;
    int nwt = gridDim.x * 4;

    // Wrad[p][b][lane], packed over basis pairs (done ONCE per warp)
    u64 Wreg2[44];
#pragma unroll
    for (int p = 0; p < 11; p++)
#pragma unroll
        for (int i = 0; i < 4; i++) {
            float lo = Wrad[(p * 8 + 2 * i) * 32 + lane];
            float hi = Wrad[(p * 8 + 2 * i + 1) * 32 + lane];
            PACK2(Wreg2[p * 4 + i], lo, hi);
        }

    for (int n = gwarp; n < N; n += nwt) {
        float A0 = 0.0f;
        float A1[3] = {0.0f, 0.0f, 0.0f};
        float A2[9] = {0.0f, 0.0f, 0.0f, 0.0f, 0.0f, 0.0f, 0.0f, 0.0f, 0.0f};

        int beg = g_off[n];
        int end = g_off[n + 1];

        for (int k0 = beg; k0 < end; k0 += 32) {
            int cnt = min(32, end - k0);
            int pos = k0 + lane;
            int eL = g_edge[(pos < end) ? pos : (end - 1)];
            int jL = idx_j[eL];

            for (int kk = 0; kk < cnt; kk++) {
                int e = __shfl_sync(0xffffffffu, eL, kk);
                int j = __shfl_sync(0xffffffffu, jL, kk);
                int jc = j * 32 + lane;

                // broadcast loads of precomputed edge data (same addr all lanes)
                float4 q0 = g_edata[e * 3 + 0];
                float4 q1 = g_edata[e * 3 + 1];
                float4 q2 = g_edata[e * 3 + 2];

                // channel gathers (issued early, consumed after w chain)
                float g0 = node0[jc];
                float g1v[3];
#pragma unroll
                for (int a = 0; a < 3; a++) g1v[a] = g_n1T[a][jc];
                float g2[9];
#pragma unroll
                for (int k = 0; k < 9; k++) g2[k] = g_n2T[k][jc];

                float h0 = q0.x, h1 = q0.y, h2 = q0.z;

                // basis values, packed over pairs
                u64 rb2[4];
                PACK2(rb2[0], q0.w, q1.x);
                PACK2(rb2[1], q1.y, q1.z);
                PACK2(rb2[2], q1.w, q2.x);
                PACK2(rb2[3], q2.y, q2.z);

                // w[p] = sum_b rb[b] * W[p,b]
                float w[11];
#pragma unroll
                for (int p = 0; p < 11; p++) {
                    u64 acc = 0ull;
#pragma unroll
                    for (int i = 0; i < 4; i++) FMA2(acc, rb2[i], Wreg2[p * 4 + i], acc);
                    w[p] = hadd2(acc);
                }

                float hh[3] = {h0, h1, h2};
                float d1 = g1v[0] * h0 + g1v[1] * h1 + g1v[2] * h2;
                float d2[3];
#pragma unroll
                for (int a = 0; a < 3; a++)
                    d2[a] = g2[a * 3 + 0] * h0 + g2[a * 3 + 1] * h1 + g2[a * 3 + 2] * h2;
                float q = d2[0] * h0 + d2[1] * h1 + d2[2] * h2;

                A0 += g0 * w[0] + d1 * w[4] + q * w[9];

                float s01 = g0 * w[1] + d1 * w[6];
#pragma unroll
                for (int a = 0; a < 3; a++)
                    A1[a] += s01 * hh[a] + g1v[a] * w[3] + d2[a] * w[8];

                float gw2 = g0 * w[2];
#pragma unroll
                for (int a = 0; a < 3; a++) {
                    float pre = gw2 * hh[a] + g1v[a] * w[5] + d2[a] * w[10];
#pragma unroll
                    for (int b = 0; b < 3; b++)
                        A2[a * 3 + b] += pre * hh[b] + g2[a * 3 + b] * w[7];
                }
            }
        }

        const float norm = 1.0f / 16.0f;
        int i0 = n * 32 + lane;
        g_A0[i0] = A0 * norm;
#pragma unroll
        for (int a = 0; a < 3; a++) g_A1[a][i0] = A1[a] * norm;
#pragma unroll
        for (int k = 0; k < 9; k++) g_A2[k][i0] = A2[k] * norm;
    }
}

// ---------------------------------------------------------------------------
// Node kernel: 128-thread blocks @ occ2 (256-reg budget), 4 warps/CTA,
// TWO nodes per warp sharing every weight LDS.128. Quad c-loop in f32x2.
// ---------------------------------------------------------------------------
#define NWARPS 4

__global__ __launch_bounds__(128, 2)
void node_kernel(const float* __restrict__ node0,
                 const float* __restrict__ U,
                 const float* __restrict__ V,
                 const float* __restrict__ Wg,
                 float* __restrict__ out,
                 int N)
{
    extern __shared__ float sh[];
    float* sWm = sh;                           // 11*1024 quad-interleaved
    float* sWg = sWm + 11264;                  // 3*1024 quad-interleaved
    float* sX  = sWg + 3072;                   // NWARPS * 2 * 27 * 32

    // quad interleave: idx = m*1024 + (c>>2)*128 + d*4 + (c&3)
    for (int i = threadIdx.x; i < 11 * 1024; i += blockDim.x) {
        float v = (i < 3 * 1024) ? U[i] : V[i - 3 * 1024];
        int m = i >> 10, c = (i >> 5) & 31, d = i & 31;
        sWm[(m << 10) + ((c >> 2) << 7) + (d << 2) + (c & 3)] = v;
    }
    for (int i = threadIdx.x; i < 3 * 1024; i += blockDim.x) {
        int m = i >> 10, c = (i >> 5) & 31, d = i & 31;
        sWg[(m << 10) + ((c >> 2) << 7) + (d << 2) + (c & 3)] = Wg[i];
    }
    __syncthreads();

    int warp = threadIdx.x >> 5;
    int lane = threadIdx.x & 31;
    int gwarp = blockIdx.x * NWARPS + warp;
    int nwt = gridDim.x * NWARPS;

    int d = lane;
    const float4* wm4 = (const float4*)sWm;    // idx: m*256 + cq*32 + d
    const float4* wg4 = (const float4*)sWg;
    float* Xs0 = sX + warp * 2 * 27 * 32;
    float* Xs1 = Xs0 + 27 * 32;

    int npairs = (N + 1) / 2;
    for (int np = gwarp; np < npairs; np += nwt) {
        int n0 = 2 * np;
        int n1 = (2 * np + 1 < N) ? (2 * np + 1) : n0;

        // ---- stage x for both nodes ----
#pragma unroll
        for (int half = 0; half < 2; half++) {
            int n = half ? n1 : n0;
            float* Xs = half ? Xs1 : Xs0;
            int i0 = n * 32 + lane;
            float a0 = g_A0[i0];
            float a1[3];
#pragma unroll
            for (int a = 0; a < 3; a++) a1[a] = g_A1[a][i0];
            float a2[9];
#pragma unroll
            for (int k = 0; k < 9; k++) a2[k] = g_A2[k][i0];

            float s1 = a1[0] * a1[0] + a1[1] * a1[1] + a1[2] * a1[2];
            float s2 = 0.0f;
#pragma unroll
            for (int k = 0; k < 9; k++) s2 += a2[k] * a2[k];
            float t[3];
#pragma unroll
            for (int b = 0; b < 3; b++)
                t[b] = a1[0] * a2[0 * 3 + b] + a1[1] * a2[1 * 3 + b] + a1[2] * a2[2 * 3 + b];
            float r[9];
#pragma unroll
            for (int a = 0; a < 3; a++)
#pragma unroll
                for (int b = 0; b < 3; b++)
                    r[a * 3 + b] = a2[a * 3 + 0] * a2[0 * 3 + b]
                                 + a2[a * 3 + 1] * a2[1 * 3 + b]
                                 + a2[a * 3 + 2] * a2[2 * 3 + b];

            Xs[0 * 32 + lane] = a0;
            Xs[1 * 32 + lane] = s1;
            Xs[2 * 32 + lane] = s2;
#pragma unroll
            for (int a = 0; a < 3; a++) { Xs[(3 + a) * 32 + lane] = a1[a]; Xs[(6 + a) * 32 + lane] = t[a]; }
#pragma unroll
            for (int k = 0; k < 9; k++) { Xs[(9 + k) * 32 + lane] = a2[k]; Xs[(18 + k) * 32 + lane] = r[k]; }
        }
        __syncwarp();

        u64 y0acc[2] = {0ull, 0ull};
        u64 y1acc[2][3] = {{0ull, 0ull, 0ull}, {0ull, 0ull, 0ull}};
        u64 y2acc[2][9];
#pragma unroll
        for (int h = 0; h < 2; h++)
#pragma unroll
            for (int k = 0; k < 9; k++) y2acc[h][k] = 0ull;

        const float4* X4a = (const float4*)Xs0;
        const float4* X4b = (const float4*)Xs1;

        for (int cq = 0; cq < 8; cq++) {
            int wq = cq * 32 + d;

            // ---- weight quads loaded ONCE for both nodes ----
            float4 w0q = wm4[0 * 256 + wq];
            float4 w3q = wm4[3 * 256 + wq];
            float4 w6q = wm4[6 * 256 + wq];
            float4 w9q = wm4[9 * 256 + wq];
            float4 wU1 = wm4[1 * 256 + wq];
            float4 wV1 = wm4[4 * 256 + wq];
            float4 wV5 = wm4[8 * 256 + wq];
            float4 wU2 = wm4[2 * 256 + wq];
            float4 wV2 = wm4[5 * 256 + wq];
            float4 wV4 = wm4[7 * 256 + wq];
            float4 wV7 = wm4[10 * 256 + wq];

#pragma unroll
            for (int h = 0; h < 2; h++) {
                const float4* X4 = h ? X4b : X4a;

                float4 xa0q = X4[0 * 8 + cq];
                u64 xa0lo, xa0hi; SPLIT4(xa0lo, xa0hi, xa0q);
                u64 wl, wh;
                {
                    SPLIT4(wl, wh, w0q);
                    FMA2(y0acc[h], xa0lo, wl, y0acc[h]); FMA2(y0acc[h], xa0hi, wh, y0acc[h]);
                    u64 sqlo, sqhi; MUL2(sqlo, xa0lo, xa0lo); MUL2(sqhi, xa0hi, xa0hi);
                    SPLIT4(wl, wh, w3q);
                    FMA2(y0acc[h], sqlo, wl, y0acc[h]); FMA2(y0acc[h], sqhi, wh, y0acc[h]);
                    float4 xs1q = X4[1 * 8 + cq];
                    u64 xl, xh; SPLIT4(xl, xh, xs1q);
                    SPLIT4(wl, wh, w6q);
                    FMA2(y0acc[h], xl, wl, y0acc[h]); FMA2(y0acc[h], xh, wh, y0acc[h]);
                    float4 xs2q = X4[2 * 8 + cq];
                    SPLIT4(xl, xh, xs2q);
                    SPLIT4(wl, wh, w9q);
                    FMA2(y0acc[h], xl, wl, y0acc[h]); FMA2(y0acc[h], xh, wh, y0acc[h]);
                }

                u64 xa1lo[3], xa1hi[3];
                {
                    u64 u1l, u1h; SPLIT4(u1l, u1h, wU1);
                    u64 v1l, v1h; SPLIT4(v1l, v1h, wV1);
                    u64 v5l, v5h; SPLIT4(v5l, v5h, wV5);
#pragma unroll
                    for (int a = 0; a < 3; a++) {
                        float4 xq = X4[(3 + a) * 8 + cq];
                        SPLIT4(xa1lo[a], xa1hi[a], xq);
                        float4 xtq = X4[(6 + a) * 8 + cq];
                        u64 tl, th; SPLIT4(tl, th, xtq);
                        FMA2(y1acc[h][a], xa1lo[a], u1l, y1acc[h][a]);
                        FMA2(y1acc[h][a], xa1hi[a], u1h, y1acc[h][a]);
                        u64 pl, ph;
                        MUL2(pl, xa0lo, xa1lo[a]); MUL2(ph, xa0hi, xa1hi[a]);
                        FMA2(y1acc[h][a], pl, v1l, y1acc[h][a]);
                        FMA2(y1acc[h][a], ph, v1h, y1acc[h][a]);
                        FMA2(y1acc[h][a], tl, v5l, y1acc[h][a]);
                        FMA2(y1acc[h][a], th, v5h, y1acc[h][a]);
                    }
                }

                {
                    u64 u2l, u2h; SPLIT4(u2l, u2h, wU2);
                    u64 v2l, v2h; SPLIT4(v2l, v2h, wV2);
                    u64 v4l, v4h; SPLIT4(v4l, v4h, wV4);
                    u64 v7l, v7h; SPLIT4(v7l, v7h, wV7);
#pragma unroll
                    for (int a = 0; a < 3; a++) {
#pragma unroll
                        for (int b = 0; b < 3; b++) {
                            int k = a * 3 + b;
                            float4 xa2q = X4[(9 + k) * 8 + cq];
                            u64 x2l, x2h; SPLIT4(x2l, x2h, xa2q);
                            float4 xrq = X4[(18 + k) * 8 + cq];
                            u64 xrl, xrh; SPLIT4(xrl, xrh, xrq);
                            FMA2(y2acc[h][k], x2l, u2l, y2acc[h][k]);
                            FMA2(y2acc[h][k], x2h, u2h, y2acc[h][k]);
                            u64 pl, ph;
                            MUL2(pl, xa0lo, x2l); MUL2(ph, xa0hi, x2h);
                            FMA2(y2acc[h][k], pl, v2l, y2acc[h][k]);
                            FMA2(y2acc[h][k], ph, v2h, y2acc[h][k]);
                            MUL2(pl, xa1lo[a], xa1lo[b]); MUL2(ph, xa1hi[a], xa1hi[b]);
                            FMA2(y2acc[h][k], pl, v4l, y2acc[h][k]);
                            FMA2(y2acc[h][k], ph, v4h, y2acc[h][k]);
                            FMA2(y2acc[h][k], xrl, v7l, y2acc[h][k]);
                            FMA2(y2acc[h][k], xrh, v7h, y2acc[h][k]);
                        }
                    }
                }
            }
        }

        // gate projections: y0 broadcast via Xs row 0 (x no longer needed)
        float y0v[2];
        y0v[0] = hadd2(y0acc[0]);
        y0v[1] = hadd2(y0acc[1]);
        __syncwarp();
        Xs0[lane] = y0v[0];
        Xs1[lane] = y0v[1];
        __syncwarp();

        u64 gp0a[2] = {0ull, 0ull}, gp1a[2] = {0ull, 0ull}, gp2a[2] = {0ull, 0ull};
        for (int cq = 0; cq < 8; cq++) {
            int wq = cq * 32 + d;
            float4 w0v = wg4[0 * 256 + wq];
            float4 w1v = wg4[1 * 256 + wq];
            float4 w2v = wg4[2 * 256 + wq];
#pragma unroll
            for (int h = 0; h < 2; h++) {
                float4 yq = *(const float4*)((h ? Xs1 : Xs0) + cq * 4);
                u64 yl, yh; SPLIT4(yl, yh, yq);
                u64 wl, wh;
                SPLIT4(wl, wh, w0v);
                FMA2(gp0a[h], yl, wl, gp0a[h]); FMA2(gp0a[h], yh, wh, gp0a[h]);
                SPLIT4(wl, wh, w1v);
                FMA2(gp1a[h], yl, wl, gp1a[h]); FMA2(gp1a[h], yh, wh, gp1a[h]);
                SPLIT4(wl, wh, w2v);
                FMA2(gp2a[h], yl, wl, gp2a[h]); FMA2(gp2a[h], yh, wh, gp2a[h]);
            }
        }

        float* out0 = out;
        float* out1 = out + (size_t)N * 32;
        float* out2 = out + (size_t)N * 32 * 4;

#pragma unroll
        for (int h = 0; h < 2; h++) {
            int n = h ? n1 : n0;
            if (h == 1 && n1 == n0) break;
            int i0 = n * 32 + lane;
            float gp0 = hadd2(gp0a[h]), gp1 = hadd2(gp1a[h]), gp2 = hadd2(gp2a[h]);
            float gate0 = gp0 / (1.0f + __expf(-gp0));
            float gate1 = gp1 / (1.0f + __expf(-gp1));
            float gate2 = gp2 / (1.0f + __expf(-gp2));

            float y1[3], y2[9];
#pragma unroll
            for (int a = 0; a < 3; a++) y1[a] = hadd2(y1acc[h][a]);
#pragma unroll
            for (int k = 0; k < 9; k++) y2[k] = hadd2(y2acc[h][k]);

            out0[i0] = node0[i0] + gate0;
            float* o1p = out1 + (size_t)i0 * 3;
#pragma unroll
            for (int a = 0; a < 3; a++) o1p[a] = g_n1T[a][i0] + y1[a] * gate1;
            float* o2p = out2 + (size_t)i0 * 9;
#pragma unroll
            for (int k = 0; k < 9; k++) o2p[k] = g_n2T[k][i0] + y2[k] * gate2;
        }
        __syncwarp();
    }
}

// ---------------------------------------------------------------------------
extern "C" void kernel_launch(void* const* d_in, const int* in_sizes, int n_in,
                              void* d_out, int out_size)
{
    const float* node0 = (const float*)d_in[0];
    const float* node1 = (const float*)d_in[1];
    const float* node2 = (const float*)d_in[2];
    const float* rij   = (const float*)d_in[3];
    const float* Wrad  = (const float*)d_in[4];
    const float* U     = (const float*)d_in[5];
    const float* V     = (const float*)d_in[6];
    const float* Wg    = (const float*)d_in[7];
    const int*   idx_i = (const int*)d_in[8];
    const int*   idx_j = (const int*)d_in[9];
    float* out = (float*)d_out;

    int N = in_sizes[0] / 32;
    int E = in_sizes[8];
    int NC = N * 32;
    int GMAX = (E > NC) ? E : NC;

    int node_smem = (11264 + 3072 + NWARPS * 2 * 27 * 32) * (int)sizeof(float);
    cudaFuncSetAttribute(node_kernel, cudaFuncAttributeMaxDynamicSharedMemorySize, node_smem);

    // zero g_deg via memset node (keeps edge_kernel at ncu's captured launch slot)
    void* degPtr = nullptr;
    cudaGetSymbolAddress(&degPtr, g_deg);
    cudaMemsetAsync(degPtr, 0, (size_t)N * sizeof(int));

    hist_transpose_kernel<<<(GMAX + 255) / 256, 256>>>(idx_i, node1, node2, E, NC);
    scan_kernel<<<1, 1024>>>(N, E);
    scatter_pre_kernel<<<(E + 255) / 256, 256>>>(idx_i, rij, E);
    edge_kernel<<<444, 128>>>(node0, Wrad, idx_j, N);
    node_kernel<<<296, 128, node_smem>>>(node0, U, V, Wg, out, N);
}

// round 13
// speedup vs baseline: 1.1607x; 1.1607x over previous
#include <cuda_runtime.h>
#include <math.h>

typedef unsigned long long u64;

#define NMAX 20000
#define EMAX 320000
#define N32  (NMAX * 32)

// f32x2 packed helpers
#define FMA2(d, a, b, c) asm("fma.rn.f32x2 %0, %1, %2, %3;" : "=l"(d) : "l"(a), "l"(b), "l"(c))
#define MUL2(d, a, b)    asm("mul.rn.f32x2 %0, %1, %2;" : "=l"(d) : "l"(a), "l"(b))
#define PACK2(d, lo, hi) asm("mov.b64 %0, {%1, %2};" : "=l"(d) : "f"(lo), "f"(hi))
#define UNPACK2(lo, hi, s) asm("mov.b64 {%0, %1}, %2;" : "=f"(lo), "=f"(hi) : "l"(s))

__device__ __forceinline__ float hadd2(u64 v) {
    float lo, hi; UNPACK2(lo, hi, v); return lo + hi;
}

// CSR build scratch
__device__ int g_deg[NMAX];
__device__ int g_off[NMAX + 1];
__device__ int g_cur[NMAX];
__device__ int g_edge[EMAX];

// per-edge precomputed data: {h0,h1,h2,rb0},{rb1,rb2,rb3,rb4},{rb5,rb6,rb7,pad}
__device__ float4 g_edata[EMAX * 3];

// transposed node features (plane-major for coalesced gather)
__device__ float g_n1T[3][N32];
__device__ float g_n2T[9][N32];

// ---------------------------------------------------------------------------
// fused histogram + feature transpose
__global__ void hist_transpose_kernel(const int* __restrict__ idx_i,
                                      const float* __restrict__ node1,
                                      const float* __restrict__ node2,
                                      int E, int NC) {
    int i = blockIdx.x * blockDim.x + threadIdx.x;
    if (i < E) atomicAdd(&g_deg[idx_i[i]], 1);
    if (i < NC) {
#pragma unroll
        for (int a = 0; a < 3; a++) g_n1T[a][i] = node1[(size_t)i * 3 + a];
#pragma unroll
        for (int k = 0; k < 9; k++) g_n2T[k][i] = node2[(size_t)i * 9 + k];
    }
}

__global__ void scan_kernel(int N, int E) {
    __shared__ int ssum[1024];
    int t = threadIdx.x;
    int chunk = (N + 1023) / 1024;
    int base = t * chunk;
    int s = 0;
    for (int k = 0; k < chunk; k++) {
        int idx = base + k;
        if (idx < N) s += g_deg[idx];
    }
    ssum[t] = s;
    __syncthreads();
    for (int off = 1; off < 1024; off <<= 1) {
        int v = (t >= off) ? ssum[t - off] : 0;
        __syncthreads();
        ssum[t] += v;
        __syncthreads();
    }
    int run = ssum[t] - s;
    for (int k = 0; k < chunk; k++) {
        int idx = base + k;
        if (idx < N) {
            int d = g_deg[idx];
            g_off[idx] = run;
            g_cur[idx] = run;
            run += d;
        }
    }
    if (t == 0) g_off[N] = E;
}

// fused CSR scatter + per-edge geometry/rbf precompute
__global__ void scatter_pre_kernel(const int* __restrict__ idx_i,
                                   const float* __restrict__ rij,
                                   int E) {
    int e = blockIdx.x * blockDim.x + threadIdx.x;
    if (e >= E) return;

    int p = atomicAdd(&g_cur[idx_i[e]], 1);
    g_edge[p] = e;

    float rx = rij[3 * e + 0];
    float ry = rij[3 * e + 1];
    float rz = rij[3 * e + 2];
    float dd = rx * rx + ry * ry + rz * rz + 1e-12f;
    float iv = rsqrtf(dd);
    float dist = dd * iv;
    float h0 = rx * iv, h1 = ry * iv, h2 = rz * iv;

    float uu = fminf(dist * 0.2f, 1.0f);
    float fc = 0.5f * (__cosf(3.14159265358979323846f * uu) + 1.0f);

    float rb[8];
#pragma unroll
    for (int b = 0; b < 8; b++) {
        float cb = 0.5f + (float)b * (4.5f / 7.0f);
        float dl = dist - cb;
        rb[b] = __expf(-4.0f * dl * dl) * fc;
    }

    g_edata[e * 3 + 0] = make_float4(h0, h1, h2, rb[0]);
    g_edata[e * 3 + 1] = make_float4(rb[1], rb[2], rb[3], rb[4]);
    g_edata[e * 3 + 2] = make_float4(rb[5], rb[6], rb[7], 0.0f);
}

// ---------------------------------------------------------------------------
// FUSED kernel: persistent warps, grid-stride over nodes; lane = channel.
// Per node: edge phase (R10 loop, accumulators in registers) immediately
// followed by self-interaction + gates + output — no g_A round trip, and
// node-phase work from some warps fills idle issue slots of others' edge
// phases.
// ---------------------------------------------------------------------------
#define NWARPS 4

__global__ __launch_bounds__(128, 3)
void fused_kernel(const float* __restrict__ node0,
                  const float* __restrict__ Wrad,
                  const float* __restrict__ U,
                  const float* __restrict__ V,
                  const float* __restrict__ Wg,
                  const int* __restrict__ idx_j,
                  float* __restrict__ out,
                  int N)
{
    extern __shared__ float sh[];
    float* sWm = sh;                           // 11*1024 pair-interleaved
    float* sWg = sWm + 11264;                  // 3*1024 pair-interleaved
    float* sX  = sWg + 3072;                   // NWARPS * 27 * 32
    float* sY  = sX + NWARPS * 27 * 32;        // NWARPS * 32

    // pair interleave: idx = m*1024 + (c>>1)*64 + d*2 + (c&1)
    for (int i = threadIdx.x; i < 11 * 1024; i += blockDim.x) {
        float v = (i < 3 * 1024) ? U[i] : V[i - 3 * 1024];
        int m = i >> 10, c = (i >> 5) & 31, d = i & 31;
        sWm[(m << 10) + ((c >> 1) << 6) + (d << 1) + (c & 1)] = v;
    }
    for (int i = threadIdx.x; i < 3 * 1024; i += blockDim.x) {
        int m = i >> 10, c = (i >> 5) & 31, d = i & 31;
        sWg[(m << 10) + ((c >> 1) << 6) + (d << 1) + (c & 1)] = Wg[i];
    }
    __syncthreads();

    int warp = threadIdx.x >> 5;
    int lane = threadIdx.x & 31;
    int gwarp = blockIdx.x * NWARPS + warp;
    int nwt = gridDim.x * NWARPS;

    // Wrad[p][b][lane], packed over basis pairs (done ONCE per warp)
    u64 Wreg2[44];
#pragma unroll
    for (int p = 0; p < 11; p++)
#pragma unroll
        for (int i = 0; i < 4; i++) {
            float lo = Wrad[(p * 8 + 2 * i) * 32 + lane];
            float hi = Wrad[(p * 8 + 2 * i + 1) * 32 + lane];
            PACK2(Wreg2[p * 4 + i], lo, hi);
        }

    int d = lane;
    const u64* wm64 = (const u64*)sWm;         // idx: m*512 + cp*32 + d
    const u64* wg64 = (const u64*)sWg;
    float* Xs = sX + warp * 27 * 32;
    float* Ys = sY + warp * 32;

    for (int n = gwarp; n < N; n += nwt) {
        // ================= EDGE PHASE =================
        float A0 = 0.0f;
        float A1[3] = {0.0f, 0.0f, 0.0f};
        float A2[9] = {0.0f, 0.0f, 0.0f, 0.0f, 0.0f, 0.0f, 0.0f, 0.0f, 0.0f};

        int beg = g_off[n];
        int end = g_off[n + 1];

        for (int k0 = beg; k0 < end; k0 += 32) {
            int cnt = min(32, end - k0);
            int pos = k0 + lane;
            int eL = g_edge[(pos < end) ? pos : (end - 1)];
            int jL = idx_j[eL];

            for (int kk = 0; kk < cnt; kk++) {
                int e = __shfl_sync(0xffffffffu, eL, kk);
                int j = __shfl_sync(0xffffffffu, jL, kk);
                int jc = j * 32 + lane;

                // broadcast loads of precomputed edge data (same addr all lanes)
                float4 q0 = g_edata[e * 3 + 0];
                float4 q1 = g_edata[e * 3 + 1];
                float4 q2 = g_edata[e * 3 + 2];

                // channel gathers (issued early, consumed after w chain)
                float g0 = node0[jc];
                float g1v[3];
#pragma unroll
                for (int a = 0; a < 3; a++) g1v[a] = g_n1T[a][jc];
                float g2[9];
#pragma unroll
                for (int k = 0; k < 9; k++) g2[k] = g_n2T[k][jc];

                float h0 = q0.x, h1 = q0.y, h2 = q0.z;

                // basis values, packed over pairs
                u64 rb2[4];
                PACK2(rb2[0], q0.w, q1.x);
                PACK2(rb2[1], q1.y, q1.z);
                PACK2(rb2[2], q1.w, q2.x);
                PACK2(rb2[3], q2.y, q2.z);

                // w[p] = sum_b rb[b] * W[p,b]
                float w[11];
#pragma unroll
                for (int p = 0; p < 11; p++) {
                    u64 acc = 0ull;
#pragma unroll
                    for (int i = 0; i < 4; i++) FMA2(acc, rb2[i], Wreg2[p * 4 + i], acc);
                    w[p] = hadd2(acc);
                }

                float hh[3] = {h0, h1, h2};
                float d1 = g1v[0] * h0 + g1v[1] * h1 + g1v[2] * h2;
                float d2[3];
#pragma unroll
                for (int a = 0; a < 3; a++)
                    d2[a] = g2[a * 3 + 0] * h0 + g2[a * 3 + 1] * h1 + g2[a * 3 + 2] * h2;
                float q = d2[0] * h0 + d2[1] * h1 + d2[2] * h2;

                A0 += g0 * w[0] + d1 * w[4] + q * w[9];

                float s01 = g0 * w[1] + d1 * w[6];
#pragma unroll
                for (int a = 0; a < 3; a++)
                    A1[a] += s01 * hh[a] + g1v[a] * w[3] + d2[a] * w[8];

                float gw2 = g0 * w[2];
#pragma unroll
                for (int a = 0; a < 3; a++) {
                    float pre = gw2 * hh[a] + g1v[a] * w[5] + d2[a] * w[10];
#pragma unroll
                    for (int b = 0; b < 3; b++)
                        A2[a * 3 + b] += pre * hh[b] + g2[a * 3 + b] * w[7];
                }
            }
        }

        const float norm = 1.0f / 16.0f;
        float a0 = A0 * norm;
        float a1[3];
#pragma unroll
        for (int a = 0; a < 3; a++) a1[a] = A1[a] * norm;
        float a2[9];
#pragma unroll
        for (int k = 0; k < 9; k++) a2[k] = A2[k] * norm;

        // ================= NODE PHASE =================
        float s1 = a1[0] * a1[0] + a1[1] * a1[1] + a1[2] * a1[2];
        float s2 = 0.0f;
#pragma unroll
        for (int k = 0; k < 9; k++) s2 += a2[k] * a2[k];
        float t[3];
#pragma unroll
        for (int b = 0; b < 3; b++)
            t[b] = a1[0] * a2[0 * 3 + b] + a1[1] * a2[1 * 3 + b] + a1[2] * a2[2 * 3 + b];
        float r[9];
#pragma unroll
        for (int a = 0; a < 3; a++)
#pragma unroll
            for (int b = 0; b < 3; b++)
                r[a * 3 + b] = a2[a * 3 + 0] * a2[0 * 3 + b]
                             + a2[a * 3 + 1] * a2[1 * 3 + b]
                             + a2[a * 3 + 2] * a2[2 * 3 + b];

        Xs[0 * 32 + lane] = a0;
        Xs[1 * 32 + lane] = s1;
        Xs[2 * 32 + lane] = s2;
#pragma unroll
        for (int a = 0; a < 3; a++) { Xs[(3 + a) * 32 + lane] = a1[a]; Xs[(6 + a) * 32 + lane] = t[a]; }
#pragma unroll
        for (int k = 0; k < 9; k++) { Xs[(9 + k) * 32 + lane] = a2[k]; Xs[(18 + k) * 32 + lane] = r[k]; }
        __syncwarp();

        u64 y0acc = 0ull;
        u64 y1acc[3] = {0ull, 0ull, 0ull};
        u64 y2acc[9] = {0ull, 0ull, 0ull, 0ull, 0ull, 0ull, 0ull, 0ull, 0ull};

#pragma unroll 2
        for (int cp = 0; cp < 16; cp++) {
            int c = cp * 2;
            int wb = cp * 32 + d;

            u64 xa0p = *(const u64*)(Xs + 0 * 32 + c);
            u64 xs1p = *(const u64*)(Xs + 1 * 32 + c);
            u64 xs2p = *(const u64*)(Xs + 2 * 32 + c);

            FMA2(y0acc, xa0p, wm64[0 * 512 + wb], y0acc);
            u64 xa0sq; MUL2(xa0sq, xa0p, xa0p);
            FMA2(y0acc, xa0sq, wm64[3 * 512 + wb], y0acc);
            FMA2(y0acc, xs1p, wm64[6 * 512 + wb], y0acc);
            FMA2(y0acc, xs2p, wm64[9 * 512 + wb], y0acc);

            u64 wU1 = wm64[1 * 512 + wb];
            u64 wV1 = wm64[4 * 512 + wb];
            u64 wV5 = wm64[8 * 512 + wb];
            u64 xa1p[3];
#pragma unroll
            for (int a = 0; a < 3; a++) {
                xa1p[a] = *(const u64*)(Xs + (3 + a) * 32 + c);
                u64 xtp = *(const u64*)(Xs + (6 + a) * 32 + c);
                FMA2(y1acc[a], xa1p[a], wU1, y1acc[a]);
                u64 p01; MUL2(p01, xa0p, xa1p[a]);
                FMA2(y1acc[a], p01, wV1, y1acc[a]);
                FMA2(y1acc[a], xtp, wV5, y1acc[a]);
            }

            u64 wU2 = wm64[2 * 512 + wb];
            u64 wV2 = wm64[5 * 512 + wb];
            u64 wV4 = wm64[7 * 512 + wb];
            u64 wV7 = wm64[10 * 512 + wb];
#pragma unroll
            for (int a = 0; a < 3; a++) {
#pragma unroll
                for (int b = 0; b < 3; b++) {
                    int k = a * 3 + b;
                    u64 xa2p = *(const u64*)(Xs + (9 + k) * 32 + c);
                    u64 xrp  = *(const u64*)(Xs + (18 + k) * 32 + c);
                    FMA2(y2acc[k], xa2p, wU2, y2acc[k]);
                    u64 p02; MUL2(p02, xa0p, xa2p);
                    FMA2(y2acc[k], p02, wV2, y2acc[k]);
                    u64 p11; MUL2(p11, xa1p[a], xa1p[b]);
                    FMA2(y2acc[k], p11, wV4, y2acc[k]);
                    FMA2(y2acc[k], xrp, wV7, y2acc[k]);
                }
            }
        }

        float y0 = hadd2(y0acc);
        float y1[3], y2[9];
#pragma unroll
        for (int a = 0; a < 3; a++) y1[a] = hadd2(y1acc[a]);
#pragma unroll
        for (int k = 0; k < 9; k++) y2[k] = hadd2(y2acc[k]);

        // gates
        Ys[d] = y0;
        __syncwarp();
        u64 gp0a = 0ull, gp1a = 0ull, gp2a = 0ull;
#pragma unroll 4
        for (int cp = 0; cp < 16; cp++) {
            u64 yp = *(const u64*)(Ys + cp * 2);
            int wb = cp * 32 + d;
            FMA2(gp0a, yp, wg64[0 * 512 + wb], gp0a);
            FMA2(gp1a, yp, wg64[1 * 512 + wb], gp1a);
            FMA2(gp2a, yp, wg64[2 * 512 + wb], gp2a);
        }
        float gp0 = hadd2(gp0a), gp1 = hadd2(gp1a), gp2 = hadd2(gp2a);
        float gate0 = gp0 / (1.0f + __expf(-gp0));
        float gate1 = gp1 / (1.0f + __expf(-gp1));
        float gate2 = gp2 / (1.0f + __expf(-gp2));

        int i0 = n * 32 + lane;
        float* out0 = out;
        float* out1 = out + (size_t)N * 32;
        float* out2 = out + (size_t)N * 32 * 4;

        out0[i0] = node0[i0] + gate0;
        float* o1p = out1 + (size_t)i0 * 3;
#pragma unroll
        for (int a = 0; a < 3; a++) o1p[a] = g_n1T[a][i0] + y1[a] * gate1;
        float* o2p = out2 + (size_t)i0 * 9;
#pragma unroll
        for (int k = 0; k < 9; k++) o2p[k] = g_n2T[k][i0] + y2[k] * gate2;
        __syncwarp();
    }
}

// ---------------------------------------------------------------------------
extern "C" void kernel_launch(void* const* d_in, const int* in_sizes, int n_in,
                              void* d_out, int out_size)
{
    const float* node0 = (const float*)d_in[0];
    const float* node1 = (const float*)d_in[1];
    const float* node2 = (const float*)d_in[2];
    const float* rij   = (const float*)d_in[3];
    const float* Wrad  = (const float*)d_in[4];
    const float* U     = (const float*)d_in[5];
    const float* V     = (const float*)d_in[6];
    const float* Wg    = (const float*)d_in[7];
    const int*   idx_i = (const int*)d_in[8];
    const int*   idx_j = (const int*)d_in[9];
    float* out = (float*)d_out;

    int N = in_sizes[0] / 32;
    int E = in_sizes[8];
    int NC = N * 32;
    int GMAX = (E > NC) ? E : NC;

    int fused_smem = (11264 + 3072 + NWARPS * 27 * 32 + NWARPS * 32) * (int)sizeof(float);
    cudaFuncSetAttribute(fused_kernel, cudaFuncAttributeMaxDynamicSharedMemorySize, fused_smem);

    // zero g_deg via memset node (keeps fused_kernel at ncu's captured launch slot)
    void* degPtr = nullptr;
    cudaGetSymbolAddress(&degPtr, g_deg);
    cudaMemsetAsync(degPtr, 0, (size_t)N * sizeof(int));

    hist_transpose_kernel<<<(GMAX + 255) / 256, 256>>>(idx_i, node1, node2, E, NC);
    scan_kernel<<<1, 1024>>>(N, E);
    scatter_pre_kernel<<<(E + 255) / 256, 256>>>(idx_i, rij, E);
    fused_kernel<<<444, 128, fused_smem>>>(node0, Wrad, U, V, Wg, idx_j, out, N);
}

// round 14
// speedup vs baseline: 1.1893x; 1.0246x over previous
#include <cuda_runtime.h>
#include <math.h>

typedef unsigned long long u64;

#define NMAX 20000
#define EMAX 320000
#define N32  (NMAX * 32)

// f32x2 packed helpers
#define FMA2(d, a, b, c) asm("fma.rn.f32x2 %0, %1, %2, %3;" : "=l"(d) : "l"(a), "l"(b), "l"(c))
#define MUL2(d, a, b)    asm("mul.rn.f32x2 %0, %1, %2;" : "=l"(d) : "l"(a), "l"(b))
#define PACK2(d, lo, hi) asm("mov.b64 %0, {%1, %2};" : "=l"(d) : "f"(lo), "f"(hi))
#define UNPACK2(lo, hi, s) asm("mov.b64 {%0, %1}, %2;" : "=f"(lo), "=f"(hi) : "l"(s))

__device__ __forceinline__ float hadd2(u64 v) {
    float lo, hi; UNPACK2(lo, hi, v); return lo + hi;
}

// CSR build scratch
__device__ int g_deg[NMAX];
__device__ int g_off[NMAX + 1];
__device__ int g_cur[NMAX];
__device__ int g_edge[EMAX];

// per-edge precomputed data: {h0,h1,h2,rb0},{rb1,rb2,rb3,rb4},{rb5,rb6,rb7,pad}
__device__ float4 g_edata[EMAX * 3];

// packed node features (plane-major float4 for wide coalesced gather)
__device__ float4 g_f0[N32];    // {node0, n1x, n1y, n1z}
__device__ float4 g_f2a[N32];   // g2[0..3]
__device__ float4 g_f2b[N32];   // g2[4..7]
__device__ float  g_f2c[N32];   // g2[8]

// ---------------------------------------------------------------------------
// fused histogram + feature packing
__global__ void hist_pack_kernel(const int* __restrict__ idx_i,
                                 const float* __restrict__ node0,
                                 const float* __restrict__ node1,
                                 const float* __restrict__ node2,
                                 int E, int NC) {
    int i = blockIdx.x * blockDim.x + threadIdx.x;
    if (i < E) atomicAdd(&g_deg[idx_i[i]], 1);
    if (i < NC) {
        const float* n1p = node1 + (size_t)i * 3;
        g_f0[i] = make_float4(node0[i], n1p[0], n1p[1], n1p[2]);
        const float* n2p = node2 + (size_t)i * 9;
        g_f2a[i] = make_float4(n2p[0], n2p[1], n2p[2], n2p[3]);
        g_f2b[i] = make_float4(n2p[4], n2p[5], n2p[6], n2p[7]);
        g_f2c[i] = n2p[8];
    }
}

__global__ void scan_kernel(int N, int E) {
    __shared__ int ssum[1024];
    int t = threadIdx.x;
    int chunk = (N + 1023) / 1024;
    int base = t * chunk;
    int s = 0;
    for (int k = 0; k < chunk; k++) {
        int idx = base + k;
        if (idx < N) s += g_deg[idx];
    }
    ssum[t] = s;
    __syncthreads();
    for (int off = 1; off < 1024; off <<= 1) {
        int v = (t >= off) ? ssum[t - off] : 0;
        __syncthreads();
        ssum[t] += v;
        __syncthreads();
    }
    int run = ssum[t] - s;
    for (int k = 0; k < chunk; k++) {
        int idx = base + k;
        if (idx < N) {
            int d = g_deg[idx];
            g_off[idx] = run;
            g_cur[idx] = run;
            run += d;
        }
    }
    if (t == 0) g_off[N] = E;
}

// fused CSR scatter + per-edge geometry/rbf precompute
__global__ void scatter_pre_kernel(const int* __restrict__ idx_i,
                                   const float* __restrict__ rij,
                                   int E) {
    int e = blockIdx.x * blockDim.x + threadIdx.x;
    if (e >= E) return;

    int p = atomicAdd(&g_cur[idx_i[e]], 1);
    g_edge[p] = e;

    float rx = rij[3 * e + 0];
    float ry = rij[3 * e + 1];
    float rz = rij[3 * e + 2];
    float dd = rx * rx + ry * ry + rz * rz + 1e-12f;
    float iv = rsqrtf(dd);
    float dist = dd * iv;
    float h0 = rx * iv, h1 = ry * iv, h2 = rz * iv;

    float uu = fminf(dist * 0.2f, 1.0f);
    float fc = 0.5f * (__cosf(3.14159265358979323846f * uu) + 1.0f);

    float rb[8];
#pragma unroll
    for (int b = 0; b < 8; b++) {
        float cb = 0.5f + (float)b * (4.5f / 7.0f);
        float dl = dist - cb;
        rb[b] = __expf(-4.0f * dl * dl) * fc;
    }

    g_edata[e * 3 + 0] = make_float4(h0, h1, h2, rb[0]);
    g_edata[e * 3 + 1] = make_float4(rb[1], rb[2], rb[3], rb[4]);
    g_edata[e * 3 + 2] = make_float4(rb[5], rb[6], rb[7], 0.0f);
}

// ---------------------------------------------------------------------------
// FUSED kernel: persistent warps, grid-stride over nodes; lane = channel.
// Edge phase with float4-packed gathers, then self-interaction + gates.
// ---------------------------------------------------------------------------
#define NWARPS 4

__global__ __launch_bounds__(128, 3)
void fused_kernel(const float* __restrict__ Wrad,
                  const float* __restrict__ U,
                  const float* __restrict__ V,
                  const float* __restrict__ Wg,
                  const int* __restrict__ idx_j,
                  float* __restrict__ out,
                  int N)
{
    extern __shared__ float sh[];
    float* sWm = sh;                           // 11*1024 pair-interleaved
    float* sWg = sWm + 11264;                  // 3*1024 pair-interleaved
    float* sX  = sWg + 3072;                   // NWARPS * 27 * 32
    float* sY  = sX + NWARPS * 27 * 32;        // NWARPS * 32

    // pair interleave: idx = m*1024 + (c>>1)*64 + d*2 + (c&1)
    for (int i = threadIdx.x; i < 11 * 1024; i += blockDim.x) {
        float v = (i < 3 * 1024) ? U[i] : V[i - 3 * 1024];
        int m = i >> 10, c = (i >> 5) & 31, d = i & 31;
        sWm[(m << 10) + ((c >> 1) << 6) + (d << 1) + (c & 1)] = v;
    }
    for (int i = threadIdx.x; i < 3 * 1024; i += blockDim.x) {
        int m = i >> 10, c = (i >> 5) & 31, d = i & 31;
        sWg[(m << 10) + ((c >> 1) << 6) + (d << 1) + (c & 1)] = Wg[i];
    }
    __syncthreads();

    int warp = threadIdx.x >> 5;
    int lane = threadIdx.x & 31;
    int gwarp = blockIdx.x * NWARPS + warp;
    int nwt = gridDim.x * NWARPS;

    // Wrad[p][b][lane], packed over basis pairs (done ONCE per warp)
    u64 Wreg2[44];
#pragma unroll
    for (int p = 0; p < 11; p++)
#pragma unroll
        for (int i = 0; i < 4; i++) {
            float lo = Wrad[(p * 8 + 2 * i) * 32 + lane];
            float hi = Wrad[(p * 8 + 2 * i + 1) * 32 + lane];
            PACK2(Wreg2[p * 4 + i], lo, hi);
        }

    int d = lane;
    const u64* wm64 = (const u64*)sWm;         // idx: m*512 + cp*32 + d
    const u64* wg64 = (const u64*)sWg;
    float* Xs = sX + warp * 27 * 32;
    float* Ys = sY + warp * 32;

    for (int n = gwarp; n < N; n += nwt) {
        // ================= EDGE PHASE =================
        float A0 = 0.0f;
        float A1[3] = {0.0f, 0.0f, 0.0f};
        float A2[9] = {0.0f, 0.0f, 0.0f, 0.0f, 0.0f, 0.0f, 0.0f, 0.0f, 0.0f};

        int beg = g_off[n];
        int end = g_off[n + 1];

        for (int k0 = beg; k0 < end; k0 += 32) {
            int cnt = min(32, end - k0);
            int pos = k0 + lane;
            int eL = g_edge[(pos < end) ? pos : (end - 1)];
            int jL = idx_j[eL];

            for (int kk = 0; kk < cnt; kk++) {
                int e = __shfl_sync(0xffffffffu, eL, kk);
                int j = __shfl_sync(0xffffffffu, jL, kk);
                int jc = j * 32 + lane;

                // broadcast loads of precomputed edge data (same addr all lanes)
                float4 q0 = g_edata[e * 3 + 0];
                float4 q1 = g_edata[e * 3 + 1];
                float4 q2 = g_edata[e * 3 + 2];

                // packed channel gathers: 3x LDG.128 + 1x LDG.32
                float4 f0 = g_f0[jc];
                float4 fa = g_f2a[jc];
                float4 fb = g_f2b[jc];
                float  fcv = g_f2c[jc];

                float g0 = f0.x;
                float g1v[3] = { f0.y, f0.z, f0.w };
                float g2[9] = { fa.x, fa.y, fa.z, fa.w,
                                fb.x, fb.y, fb.z, fb.w, fcv };

                float h0 = q0.x, h1 = q0.y, h2 = q0.z;

                // basis values, packed over pairs
                u64 rb2[4];
                PACK2(rb2[0], q0.w, q1.x);
                PACK2(rb2[1], q1.y, q1.z);
                PACK2(rb2[2], q1.w, q2.x);
                PACK2(rb2[3], q2.y, q2.z);

                // w[p] = sum_b rb[b] * W[p,b]
                float w[11];
#pragma unroll
                for (int p = 0; p < 11; p++) {
                    u64 acc = 0ull;
#pragma unroll
                    for (int i = 0; i < 4; i++) FMA2(acc, rb2[i], Wreg2[p * 4 + i], acc);
                    w[p] = hadd2(acc);
                }

                float hh[3] = {h0, h1, h2};
                float d1 = g1v[0] * h0 + g1v[1] * h1 + g1v[2] * h2;
                float d2[3];
#pragma unroll
                for (int a = 0; a < 3; a++)
                    d2[a] = g2[a * 3 + 0] * h0 + g2[a * 3 + 1] * h1 + g2[a * 3 + 2] * h2;
                float q = d2[0] * h0 + d2[1] * h1 + d2[2] * h2;

                A0 += g0 * w[0] + d1 * w[4] + q * w[9];

                float s01 = g0 * w[1] + d1 * w[6];
#pragma unroll
                for (int a = 0; a < 3; a++)
                    A1[a] += s01 * hh[a] + g1v[a] * w[3] + d2[a] * w[8];

                float gw2 = g0 * w[2];
#pragma unroll
                for (int a = 0; a < 3; a++) {
                    float pre = gw2 * hh[a] + g1v[a] * w[5] + d2[a] * w[10];
#pragma unroll
                    for (int b = 0; b < 3; b++)
                        A2[a * 3 + b] += pre * hh[b] + g2[a * 3 + b] * w[7];
                }
            }
        }

        const float norm = 1.0f / 16.0f;
        float a0 = A0 * norm;
        float a1[3];
#pragma unroll
        for (int a = 0; a < 3; a++) a1[a] = A1[a] * norm;
        float a2[9];
#pragma unroll
        for (int k = 0; k < 9; k++) a2[k] = A2[k] * norm;

        // ================= NODE PHASE =================
        float s1 = a1[0] * a1[0] + a1[1] * a1[1] + a1[2] * a1[2];
        float s2 = 0.0f;
#pragma unroll
        for (int k = 0; k < 9; k++) s2 += a2[k] * a2[k];
        float t[3];
#pragma unroll
        for (int b = 0; b < 3; b++)
            t[b] = a1[0] * a2[0 * 3 + b] + a1[1] * a2[1 * 3 + b] + a1[2] * a2[2 * 3 + b];
        float r[9];
#pragma unroll
        for (int a = 0; a < 3; a++)
#pragma unroll
            for (int b = 0; b < 3; b++)
                r[a * 3 + b] = a2[a * 3 + 0] * a2[0 * 3 + b]
                             + a2[a * 3 + 1] * a2[1 * 3 + b]
                             + a2[a * 3 + 2] * a2[2 * 3 + b];

        Xs[0 * 32 + lane] = a0;
        Xs[1 * 32 + lane] = s1;
        Xs[2 * 32 + lane] = s2;
#pragma unroll
        for (int a = 0; a < 3; a++) { Xs[(3 + a) * 32 + lane] = a1[a]; Xs[(6 + a) * 32 + lane] = t[a]; }
#pragma unroll
        for (int k = 0; k < 9; k++) { Xs[(9 + k) * 32 + lane] = a2[k]; Xs[(18 + k) * 32 + lane] = r[k]; }
        __syncwarp();

        u64 y0acc = 0ull;
        u64 y1acc[3] = {0ull, 0ull, 0ull};
        u64 y2acc[9] = {0ull, 0ull, 0ull, 0ull, 0ull, 0ull, 0ull, 0ull, 0ull};

#pragma unroll 2
        for (int cp = 0; cp < 16; cp++) {
            int c = cp * 2;
            int wb = cp * 32 + d;

            u64 xa0p = *(const u64*)(Xs + 0 * 32 + c);
            u64 xs1p = *(const u64*)(Xs + 1 * 32 + c);
            u64 xs2p = *(const u64*)(Xs + 2 * 32 + c);

            FMA2(y0acc, xa0p, wm64[0 * 512 + wb], y0acc);
            u64 xa0sq; MUL2(xa0sq, xa0p, xa0p);
            FMA2(y0acc, xa0sq, wm64[3 * 512 + wb], y0acc);
            FMA2(y0acc, xs1p, wm64[6 * 512 + wb], y0acc);
            FMA2(y0acc, xs2p, wm64[9 * 512 + wb], y0acc);

            u64 wU1 = wm64[1 * 512 + wb];
            u64 wV1 = wm64[4 * 512 + wb];
            u64 wV5 = wm64[8 * 512 + wb];
            u64 xa1p[3];
#pragma unroll
            for (int a = 0; a < 3; a++) {
                xa1p[a] = *(const u64*)(Xs + (3 + a) * 32 + c);
                u64 xtp = *(const u64*)(Xs + (6 + a) * 32 + c);
                FMA2(y1acc[a], xa1p[a], wU1, y1acc[a]);
                u64 p01; MUL2(p01, xa0p, xa1p[a]);
                FMA2(y1acc[a], p01, wV1, y1acc[a]);
                FMA2(y1acc[a], xtp, wV5, y1acc[a]);
            }

            u64 wU2 = wm64[2 * 512 + wb];
            u64 wV2 = wm64[5 * 512 + wb];
            u64 wV4 = wm64[7 * 512 + wb];
            u64 wV7 = wm64[10 * 512 + wb];
#pragma unroll
            for (int a = 0; a < 3; a++) {
#pragma unroll
                for (int b = 0; b < 3; b++) {
                    int k = a * 3 + b;
                    u64 xa2p = *(const u64*)(Xs + (9 + k) * 32 + c);
                    u64 xrp  = *(const u64*)(Xs + (18 + k) * 32 + c);
                    FMA2(y2acc[k], xa2p, wU2, y2acc[k]);
                    u64 p02; MUL2(p02, xa0p, xa2p);
                    FMA2(y2acc[k], p02, wV2, y2acc[k]);
                    u64 p11; MUL2(p11, xa1p[a], xa1p[b]);
                    FMA2(y2acc[k], p11, wV4, y2acc[k]);
                    FMA2(y2acc[k], xrp, wV7, y2acc[k]);
                }
            }
        }

        float y0 = hadd2(y0acc);
        float y1[3], y2[9];
#pragma unroll
        for (int a = 0; a < 3; a++) y1[a] = hadd2(y1acc[a]);
#pragma unroll
        for (int k = 0; k < 9; k++) y2[k] = hadd2(y2acc[k]);

        // gates
        Ys[d] = y0;
        __syncwarp();
        u64 gp0a = 0ull, gp1a = 0ull, gp2a = 0ull;
#pragma unroll 4
        for (int cp = 0; cp < 16; cp++) {
            u64 yp = *(const u64*)(Ys + cp * 2);
            int wb = cp * 32 + d;
            FMA2(gp0a, yp, wg64[0 * 512 + wb], gp0a);
            FMA2(gp1a, yp, wg64[1 * 512 + wb], gp1a);
            FMA2(gp2a, yp, wg64[2 * 512 + wb], gp2a);
        }
        float gp0 = hadd2(gp0a), gp1 = hadd2(gp1a), gp2 = hadd2(gp2a);
        float gate0 = gp0 / (1.0f + __expf(-gp0));
        float gate1 = gp1 / (1.0f + __expf(-gp1));
        float gate2 = gp2 / (1.0f + __expf(-gp2));

        int i0 = n * 32 + lane;
        float* out0 = out;
        float* out1 = out + (size_t)N * 32;
        float* out2 = out + (size_t)N * 32 * 4;

        // residuals from packed features (4 wide loads)
        float4 f0 = g_f0[i0];
        float4 fa = g_f2a[i0];
        float4 fb = g_f2b[i0];
        float  fcv = g_f2c[i0];

        out0[i0] = f0.x + gate0;
        float* o1p = out1 + (size_t)i0 * 3;
        o1p[0] = f0.y + y1[0] * gate1;
        o1p[1] = f0.z + y1[1] * gate1;
        o1p[2] = f0.w + y1[2] * gate1;
        float* o2p = out2 + (size_t)i0 * 9;
        float n2v[9] = { fa.x, fa.y, fa.z, fa.w, fb.x, fb.y, fb.z, fb.w, fcv };
#pragma unroll
        for (int k = 0; k < 9; k++) o2p[k] = n2v[k] + y2[k] * gate2;
        __syncwarp();
    }
}

// ---------------------------------------------------------------------------
extern "C" void kernel_launch(void* const* d_in, const int* in_sizes, int n_in,
                              void* d_out, int out_size)
{
    const float* node0 = (const float*)d_in[0];
    const float* node1 = (const float*)d_in[1];
    const float* node2 = (const float*)d_in[2];
    const float* rij   = (const float*)d_in[3];
    const float* Wrad  = (const float*)d_in[4];
    const float* U     = (const float*)d_in[5];
    const float* V     = (const float*)d_in[6];
    const float* Wg    = (const float*)d_in[7];
    const int*   idx_i = (const int*)d_in[8];
    const int*   idx_j = (const int*)d_in[9];
    float* out = (float*)d_out;

    int N = in_sizes[0] / 32;
    int E = in_sizes[8];
    int NC = N * 32;
    int GMAX = (E > NC) ? E : NC;

    int fused_smem = (11264 + 3072 + NWARPS * 27 * 32 + NWARPS * 32) * (int)sizeof(float);
    cudaFuncSetAttribute(fused_kernel, cudaFuncAttributeMaxDynamicSharedMemorySize, fused_smem);

    // zero g_deg via memset node (keeps fused_kernel at ncu's captured launch slot)
    void* degPtr = nullptr;
    cudaGetSymbolAddress(&degPtr, g_deg);
    cudaMemsetAsync(degPtr, 0, (size_t)N * sizeof(int));

    hist_pack_kernel<<<(GMAX + 255) / 256, 256>>>(idx_i, node0, node1, node2, E, NC);
    scan_kernel<<<1, 1024>>>(N, E);
    scatter_pre_kernel<<<(E + 255) / 256, 256>>>(idx_i, rij, E);
    fused_kernel<<<444, 128, fused_smem>>>(Wrad, U, V, Wg, idx_j, out, N);
}

// round 15
// speedup vs baseline: 1.2387x; 1.0415x over previous
#include <cuda_runtime.h>
#include <math.h>

typedef unsigned long long u64;

#define NMAX 20000
#define EMAX 320000
#define N32  (NMAX * 32)

// f32x2 packed helpers
#define FMA2(d, a, b, c) asm("fma.rn.f32x2 %0, %1, %2, %3;" : "=l"(d) : "l"(a), "l"(b), "l"(c))
#define MUL2(d, a, b)    asm("mul.rn.f32x2 %0, %1, %2;" : "=l"(d) : "l"(a), "l"(b))
#define PACK2(d, lo, hi) asm("mov.b64 %0, {%1, %2};" : "=l"(d) : "f"(lo), "f"(hi))
#define UNPACK2(lo, hi, s) asm("mov.b64 {%0, %1}, %2;" : "=f"(lo), "=f"(hi) : "l"(s))

__device__ __forceinline__ float hadd2(u64 v) {
    float lo, hi; UNPACK2(lo, hi, v); return lo + hi;
}

// CSR build scratch
__device__ int g_deg[NMAX];
__device__ int g_off[NMAX + 1];
__device__ int g_cur[NMAX];

// CSR-ordered edge data (indexed by CSR slot p, NOT edge id):
// g_j[p] = neighbor index; g_edata[3p..3p+2] = {h,rb} precompute
__device__ int g_j[EMAX];
__device__ float4 g_edata[EMAX * 3];

// packed node features (float4 for wide coalesced gather)
__device__ float4 g_f0[N32];    // {node0, n1x, n1y, n1z}
__device__ float4 g_f2a[N32];   // g2[0..3]
__device__ float4 g_f2b[N32];   // g2[4..7]
__device__ float  g_f2c[N32];   // g2[8]

// ---------------------------------------------------------------------------
// fused histogram + feature packing
__global__ void hist_pack_kernel(const int* __restrict__ idx_i,
                                 const float* __restrict__ node0,
                                 const float* __restrict__ node1,
                                 const float* __restrict__ node2,
                                 int E, int NC) {
    int i = blockIdx.x * blockDim.x + threadIdx.x;
    if (i < E) atomicAdd(&g_deg[idx_i[i]], 1);
    if (i < NC) {
        const float* n1p = node1 + (size_t)i * 3;
        g_f0[i] = make_float4(node0[i], n1p[0], n1p[1], n1p[2]);
        const float* n2p = node2 + (size_t)i * 9;
        g_f2a[i] = make_float4(n2p[0], n2p[1], n2p[2], n2p[3]);
        g_f2b[i] = make_float4(n2p[4], n2p[5], n2p[6], n2p[7]);
        g_f2c[i] = n2p[8];
    }
}

__global__ void scan_kernel(int N, int E) {
    __shared__ int ssum[1024];
    int t = threadIdx.x;
    int chunk = (N + 1023) / 1024;
    int base = t * chunk;
    int s = 0;
    for (int k = 0; k < chunk; k++) {
        int idx = base + k;
        if (idx < N) s += g_deg[idx];
    }
    ssum[t] = s;
    __syncthreads();
    for (int off = 1; off < 1024; off <<= 1) {
        int v = (t >= off) ? ssum[t - off] : 0;
        __syncthreads();
        ssum[t] += v;
        __syncthreads();
    }
    int run = ssum[t] - s;
    for (int k = 0; k < chunk; k++) {
        int idx = base + k;
        if (idx < N) {
            int d = g_deg[idx];
            g_off[idx] = run;
            g_cur[idx] = run;
            run += d;
        }
    }
    if (t == 0) g_off[N] = E;
}

// fused CSR scatter + per-edge geometry/rbf precompute, stored in CSR order
__global__ void scatter_pre_kernel(const int* __restrict__ idx_i,
                                   const int* __restrict__ idx_j,
                                   const float* __restrict__ rij,
                                   int E) {
    int e = blockIdx.x * blockDim.x + threadIdx.x;
    if (e >= E) return;

    int p = atomicAdd(&g_cur[idx_i[e]], 1);
    g_j[p] = idx_j[e];

    float rx = rij[3 * e + 0];
    float ry = rij[3 * e + 1];
    float rz = rij[3 * e + 2];
    float dd = rx * rx + ry * ry + rz * rz + 1e-12f;
    float iv = rsqrtf(dd);
    float dist = dd * iv;
    float h0 = rx * iv, h1 = ry * iv, h2 = rz * iv;

    float uu = fminf(dist * 0.2f, 1.0f);
    float fc = 0.5f * (__cosf(3.14159265358979323846f * uu) + 1.0f);

    float rb[8];
#pragma unroll
    for (int b = 0; b < 8; b++) {
        float cb = 0.5f + (float)b * (4.5f / 7.0f);
        float dl = dist - cb;
        rb[b] = __expf(-4.0f * dl * dl) * fc;
    }

    g_edata[p * 3 + 0] = make_float4(h0, h1, h2, rb[0]);
    g_edata[p * 3 + 1] = make_float4(rb[1], rb[2], rb[3], rb[4]);
    g_edata[p * 3 + 2] = make_float4(rb[5], rb[6], rb[7], 0.0f);
}

// ---------------------------------------------------------------------------
// FUSED kernel: persistent warps, grid-stride over nodes; lane = channel.
// Edge loop is a plain sequential CSR walk — no g_edge indirection, no shfl;
// j prefetched one iteration ahead (single register).
// ---------------------------------------------------------------------------
#define NWARPS 4

__global__ __launch_bounds__(128, 3)
void fused_kernel(const float* __restrict__ Wrad,
                  const float* __restrict__ U,
                  const float* __restrict__ V,
                  const float* __restrict__ Wg,
                  float* __restrict__ out,
                  int N)
{
    extern __shared__ float sh[];
    float* sWm = sh;                           // 11*1024 pair-interleaved
    float* sWg = sWm + 11264;                  // 3*1024 pair-interleaved
    float* sX  = sWg + 3072;                   // NWARPS * 27 * 32
    float* sY  = sX + NWARPS * 27 * 32;        // NWARPS * 32

    // pair interleave: idx = m*1024 + (c>>1)*64 + d*2 + (c&1)
    for (int i = threadIdx.x; i < 11 * 1024; i += blockDim.x) {
        float v = (i < 3 * 1024) ? U[i] : V[i - 3 * 1024];
        int m = i >> 10, c = (i >> 5) & 31, d = i & 31;
        sWm[(m << 10) + ((c >> 1) << 6) + (d << 1) + (c & 1)] = v;
    }
    for (int i = threadIdx.x; i < 3 * 1024; i += blockDim.x) {
        int m = i >> 10, c = (i >> 5) & 31, d = i & 31;
        sWg[(m << 10) + ((c >> 1) << 6) + (d << 1) + (c & 1)] = Wg[i];
    }
    __syncthreads();

    int warp = threadIdx.x >> 5;
    int lane = threadIdx.x & 31;
    int gwarp = blockIdx.x * NWARPS + warp;
    int nwt = gridDim.x * NWARPS;

    // Wrad[p][b][lane], packed over basis pairs (done ONCE per warp)
    u64 Wreg2[44];
#pragma unroll
    for (int p = 0; p < 11; p++)
#pragma unroll
        for (int i = 0; i < 4; i++) {
            float lo = Wrad[(p * 8 + 2 * i) * 32 + lane];
            float hi = Wrad[(p * 8 + 2 * i + 1) * 32 + lane];
            PACK2(Wreg2[p * 4 + i], lo, hi);
        }

    int d = lane;
    const u64* wm64 = (const u64*)sWm;         // idx: m*512 + cp*32 + d
    const u64* wg64 = (const u64*)sWg;
    float* Xs = sX + warp * 27 * 32;
    float* Ys = sY + warp * 32;

    for (int n = gwarp; n < N; n += nwt) {
        // ================= EDGE PHASE =================
        float A0 = 0.0f;
        float A1[3] = {0.0f, 0.0f, 0.0f};
        float A2[9] = {0.0f, 0.0f, 0.0f, 0.0f, 0.0f, 0.0f, 0.0f, 0.0f, 0.0f};

        int beg = g_off[n];
        int end = g_off[n + 1];

        if (beg < end) {
            int jn = g_j[beg];                 // prefetch j for first edge
            for (int pos = beg; pos < end; pos++) {
                int j = jn;
                int nx = (pos + 1 < end) ? (pos + 1) : pos;
                jn = g_j[nx];

                int jc = j * 32 + lane;

                // packed channel gathers: 3x LDG.128 + 1x LDG.32
                float4 f0 = g_f0[jc];
                float4 fa = g_f2a[jc];
                float4 fb = g_f2b[jc];
                float  fcv = g_f2c[jc];

                // broadcast loads of CSR-ordered edge data
                float4 q0 = g_edata[pos * 3 + 0];
                float4 q1 = g_edata[pos * 3 + 1];
                float4 q2 = g_edata[pos * 3 + 2];

                float g0 = f0.x;
                float g1v[3] = { f0.y, f0.z, f0.w };
                float g2[9] = { fa.x, fa.y, fa.z, fa.w,
                                fb.x, fb.y, fb.z, fb.w, fcv };

                float h0 = q0.x, h1 = q0.y, h2 = q0.z;

                // basis values, packed over pairs
                u64 rb2[4];
                PACK2(rb2[0], q0.w, q1.x);
                PACK2(rb2[1], q1.y, q1.z);
                PACK2(rb2[2], q1.w, q2.x);
                PACK2(rb2[3], q2.y, q2.z);

                // w[p] = sum_b rb[b] * W[p,b]
                float w[11];
#pragma unroll
                for (int p = 0; p < 11; p++) {
                    u64 acc = 0ull;
#pragma unroll
                    for (int i = 0; i < 4; i++) FMA2(acc, rb2[i], Wreg2[p * 4 + i], acc);
                    w[p] = hadd2(acc);
                }

                float hh[3] = {h0, h1, h2};
                float d1 = g1v[0] * h0 + g1v[1] * h1 + g1v[2] * h2;
                float d2[3];
#pragma unroll
                for (int a = 0; a < 3; a++)
                    d2[a] = g2[a * 3 + 0] * h0 + g2[a * 3 + 1] * h1 + g2[a * 3 + 2] * h2;
                float q = d2[0] * h0 + d2[1] * h1 + d2[2] * h2;

                A0 += g0 * w[0] + d1 * w[4] + q * w[9];

                float s01 = g0 * w[1] + d1 * w[6];
#pragma unroll
                for (int a = 0; a < 3; a++)
                    A1[a] += s01 * hh[a] + g1v[a] * w[3] + d2[a] * w[8];

                float gw2 = g0 * w[2];
#pragma unroll
                for (int a = 0; a < 3; a++) {
                    float pre = gw2 * hh[a] + g1v[a] * w[5] + d2[a] * w[10];
#pragma unroll
                    for (int b = 0; b < 3; b++)
                        A2[a * 3 + b] += pre * hh[b] + g2[a * 3 + b] * w[7];
                }
            }
        }

        const float norm = 1.0f / 16.0f;
        float a0 = A0 * norm;
        float a1[3];
#pragma unroll
        for (int a = 0; a < 3; a++) a1[a] = A1[a] * norm;
        float a2[9];
#pragma unroll
        for (int k = 0; k < 9; k++) a2[k] = A2[k] * norm;

        // ================= NODE PHASE =================
        float s1 = a1[0] * a1[0] + a1[1] * a1[1] + a1[2] * a1[2];
        float s2 = 0.0f;
#pragma unroll
        for (int k = 0; k < 9; k++) s2 += a2[k] * a2[k];
        float t[3];
#pragma unroll
        for (int b = 0; b < 3; b++)
            t[b] = a1[0] * a2[0 * 3 + b] + a1[1] * a2[1 * 3 + b] + a1[2] * a2[2 * 3 + b];
        float r[9];
#pragma unroll
        for (int a = 0; a < 3; a++)
#pragma unroll
            for (int b = 0; b < 3; b++)
                r[a * 3 + b] = a2[a * 3 + 0] * a2[0 * 3 + b]
                             + a2[a * 3 + 1] * a2[1 * 3 + b]
                             + a2[a * 3 + 2] * a2[2 * 3 + b];

        Xs[0 * 32 + lane] = a0;
        Xs[1 * 32 + lane] = s1;
        Xs[2 * 32 + lane] = s2;
#pragma unroll
        for (int a = 0; a < 3; a++) { Xs[(3 + a) * 32 + lane] = a1[a]; Xs[(6 + a) * 32 + lane] = t[a]; }
#pragma unroll
        for (int k = 0; k < 9; k++) { Xs[(9 + k) * 32 + lane] = a2[k]; Xs[(18 + k) * 32 + lane] = r[k]; }
        __syncwarp();

        u64 y0acc = 0ull;
        u64 y1acc[3] = {0ull, 0ull, 0ull};
        u64 y2acc[9] = {0ull, 0ull, 0ull, 0ull, 0ull, 0ull, 0ull, 0ull, 0ull};

#pragma unroll 2
        for (int cp = 0; cp < 16; cp++) {
            int c = cp * 2;
            int wb = cp * 32 + d;

            u64 xa0p = *(const u64*)(Xs + 0 * 32 + c);
            u64 xs1p = *(const u64*)(Xs + 1 * 32 + c);
            u64 xs2p = *(const u64*)(Xs + 2 * 32 + c);

            FMA2(y0acc, xa0p, wm64[0 * 512 + wb], y0acc);
            u64 xa0sq; MUL2(xa0sq, xa0p, xa0p);
            FMA2(y0acc, xa0sq, wm64[3 * 512 + wb], y0acc);
            FMA2(y0acc, xs1p, wm64[6 * 512 + wb], y0acc);
            FMA2(y0acc, xs2p, wm64[9 * 512 + wb], y0acc);

            u64 wU1 = wm64[1 * 512 + wb];
            u64 wV1 = wm64[4 * 512 + wb];
            u64 wV5 = wm64[8 * 512 + wb];
            u64 xa1p[3];
#pragma unroll
            for (int a = 0; a < 3; a++) {
                xa1p[a] = *(const u64*)(Xs + (3 + a) * 32 + c);
                u64 xtp = *(const u64*)(Xs + (6 + a) * 32 + c);
                FMA2(y1acc[a], xa1p[a], wU1, y1acc[a]);
                u64 p01; MUL2(p01, xa0p, xa1p[a]);
                FMA2(y1acc[a], p01, wV1, y1acc[a]);
                FMA2(y1acc[a], xtp, wV5, y1acc[a]);
            }

            u64 wU2 = wm64[2 * 512 + wb];
            u64 wV2 = wm64[5 * 512 + wb];
            u64 wV4 = wm64[7 * 512 + wb];
            u64 wV7 = wm64[10 * 512 + wb];
#pragma unroll
            for (int a = 0; a < 3; a++) {
#pragma unroll
                for (int b = 0; b < 3; b++) {
                    int k = a * 3 + b;
                    u64 xa2p = *(const u64*)(Xs + (9 + k) * 32 + c);
                    u64 xrp  = *(const u64*)(Xs + (18 + k) * 32 + c);
                    FMA2(y2acc[k], xa2p, wU2, y2acc[k]);
                    u64 p02; MUL2(p02, xa0p, xa2p);
                    FMA2(y2acc[k], p02, wV2, y2acc[k]);
                    u64 p11; MUL2(p11, xa1p[a], xa1p[b]);
                    FMA2(y2acc[k], p11, wV4, y2acc[k]);
                    FMA2(y2acc[k], xrp, wV7, y2acc[k]);
                }
            }
        }

        float y0 = hadd2(y0acc);
        float y1[3], y2[9];
#pragma unroll
        for (int a = 0; a < 3; a++) y1[a] = hadd2(y1acc[a]);
#pragma unroll
        for (int k = 0; k < 9; k++) y2[k] = hadd2(y2acc[k]);

        // gates
        Ys[d] = y0;
        __syncwarp();
        u64 gp0a = 0ull, gp1a = 0ull, gp2a = 0ull;
#pragma unroll 4
        for (int cp = 0; cp < 16; cp++) {
            u64 yp = *(const u64*)(Ys + cp * 2);
            int wb = cp * 32 + d;
            FMA2(gp0a, yp, wg64[0 * 512 + wb], gp0a);
            FMA2(gp1a, yp, wg64[1 * 512 + wb], gp1a);
            FMA2(gp2a, yp, wg64[2 * 512 + wb], gp2a);
        }
        float gp0 = hadd2(gp0a), gp1 = hadd2(gp1a), gp2 = hadd2(gp2a);
        float gate0 = gp0 / (1.0f + __expf(-gp0));
        float gate1 = gp1 / (1.0f + __expf(-gp1));
        float gate2 = gp2 / (1.0f + __expf(-gp2));

        int i0 = n * 32 + lane;
        float* out0 = out;
        float* out1 = out + (size_t)N * 32;
        float* out2 = out + (size_t)N * 32 * 4;

        // residuals from packed features (4 wide loads)
        float4 f0 = g_f0[i0];
        float4 fa = g_f2a[i0];
        float4 fb = g_f2b[i0];
        float  fcv = g_f2c[i0];

        out0[i0] = f0.x + gate0;
        float* o1p = out1 + (size_t)i0 * 3;
        o1p[0] = f0.y + y1[0] * gate1;
        o1p[1] = f0.z + y1[1] * gate1;
        o1p[2] = f0.w + y1[2] * gate1;
        float* o2p = out2 + (size_t)i0 * 9;
        float n2v[9] = { fa.x, fa.y, fa.z, fa.w, fb.x, fb.y, fb.z, fb.w, fcv };
#pragma unroll
        for (int k = 0; k < 9; k++) o2p[k] = n2v[k] + y2[k] * gate2;
        __syncwarp();
    }
}

// ---------------------------------------------------------------------------
extern "C" void kernel_launch(void* const* d_in, const int* in_sizes, int n_in,
                              void* d_out, int out_size)
{
    const float* node0 = (const float*)d_in[0];
    const float* node1 = (const float*)d_in[1];
    const float* node2 = (const float*)d_in[2];
    const float* rij   = (const float*)d_in[3];
    const float* Wrad  = (const float*)d_in[4];
    const float* U     = (const float*)d_in[5];
    const float* V     = (const float*)d_in[6];
    const float* Wg    = (const float*)d_in[7];
    const int*   idx_i = (const int*)d_in[8];
    const int*   idx_j = (const int*)d_in[9];
    float* out = (float*)d_out;

    int N = in_sizes[0] / 32;
    int E = in_sizes[8];
    int NC = N * 32;
    int GMAX = (E > NC) ? E : NC;

    int fused_smem = (11264 + 3072 + NWARPS * 27 * 32 + NWARPS * 32) * (int)sizeof(float);
    cudaFuncSetAttribute(fused_kernel, cudaFuncAttributeMaxDynamicSharedMemorySize, fused_smem);

    // zero g_deg via memset node (keeps fused_kernel at ncu's captured launch slot)
    void* degPtr = nullptr;
    cudaGetSymbolAddress(&degPtr, g_deg);
    cudaMemsetAsync(degPtr, 0, (size_t)N * sizeof(int));

    hist_pack_kernel<<<(GMAX + 255) / 256, 256>>>(idx_i, node0, node1, node2, E, NC);
    scan_kernel<<<1, 1024>>>(N, E);
    scatter_pre_kernel<<<(E + 255) / 256, 256>>>(idx_i, idx_j, rij, E);
    fused_kernel<<<444, 128, fused_smem>>>(Wrad, U, V, Wg, out, N);
}

// round 16
// speedup vs baseline: 1.2667x; 1.0227x over previous
#include <cuda_runtime.h>
#include <math.h>

typedef unsigned long long u64;

#define NMAX 20000
#define EMAX 320000
#define N32  (NMAX * 32)

// f32x2 packed helpers
#define FMA2(d, a, b, c) asm("fma.rn.f32x2 %0, %1, %2, %3;" : "=l"(d) : "l"(a), "l"(b), "l"(c))
#define MUL2(d, a, b)    asm("mul.rn.f32x2 %0, %1, %2;" : "=l"(d) : "l"(a), "l"(b))
#define PACK2(d, lo, hi) asm("mov.b64 %0, {%1, %2};" : "=l"(d) : "f"(lo), "f"(hi))
#define UNPACK2(lo, hi, s) asm("mov.b64 {%0, %1}, %2;" : "=f"(lo), "=f"(hi) : "l"(s))

__device__ __forceinline__ float hadd2(u64 v) {
    float lo, hi; UNPACK2(lo, hi, v); return lo + hi;
}

// CSR build scratch
__device__ int g_deg[NMAX];
__device__ int g_off[NMAX + 1];
__device__ int g_cur[NMAX];

// dynamic work counter for the fused kernel
__device__ int g_next;

// CSR-ordered edge data (indexed by CSR slot p, NOT edge id)
__device__ int g_j[EMAX];
__device__ float4 g_edata[EMAX * 3];

// packed node features (float4 for wide coalesced gather)
__device__ float4 g_f0[N32];    // {node0, n1x, n1y, n1z}
__device__ float4 g_f2a[N32];   // g2[0..3]
__device__ float4 g_f2b[N32];   // g2[4..7]
__device__ float  g_f2c[N32];   // g2[8]

// ---------------------------------------------------------------------------
// fused histogram + feature packing
__global__ void hist_pack_kernel(const int* __restrict__ idx_i,
                                 const float* __restrict__ node0,
                                 const float* __restrict__ node1,
                                 const float* __restrict__ node2,
                                 int E, int NC) {
    int i = blockIdx.x * blockDim.x + threadIdx.x;
    if (i < E) atomicAdd(&g_deg[idx_i[i]], 1);
    if (i < NC) {
        const float* n1p = node1 + (size_t)i * 3;
        g_f0[i] = make_float4(node0[i], n1p[0], n1p[1], n1p[2]);
        const float* n2p = node2 + (size_t)i * 9;
        g_f2a[i] = make_float4(n2p[0], n2p[1], n2p[2], n2p[3]);
        g_f2b[i] = make_float4(n2p[4], n2p[5], n2p[6], n2p[7]);
        g_f2c[i] = n2p[8];
    }
}

__global__ void scan_kernel(int N, int E) {
    __shared__ int ssum[1024];
    int t = threadIdx.x;
    int chunk = (N + 1023) / 1024;
    int base = t * chunk;
    int s = 0;
    for (int k = 0; k < chunk; k++) {
        int idx = base + k;
        if (idx < N) s += g_deg[idx];
    }
    ssum[t] = s;
    __syncthreads();
    for (int off = 1; off < 1024; off <<= 1) {
        int v = (t >= off) ? ssum[t - off] : 0;
        __syncthreads();
        ssum[t] += v;
        __syncthreads();
    }
    int run = ssum[t] - s;
    for (int k = 0; k < chunk; k++) {
        int idx = base + k;
        if (idx < N) {
            int d = g_deg[idx];
            g_off[idx] = run;
            g_cur[idx] = run;
            run += d;
        }
    }
    if (t == 0) g_off[N] = E;
}

// fused CSR scatter + per-edge geometry/rbf precompute, stored in CSR order
__global__ void scatter_pre_kernel(const int* __restrict__ idx_i,
                                   const int* __restrict__ idx_j,
                                   const float* __restrict__ rij,
                                   int E) {
    int e = blockIdx.x * blockDim.x + threadIdx.x;
    if (e >= E) return;

    int p = atomicAdd(&g_cur[idx_i[e]], 1);
    g_j[p] = idx_j[e];

    float rx = rij[3 * e + 0];
    float ry = rij[3 * e + 1];
    float rz = rij[3 * e + 2];
    float dd = rx * rx + ry * ry + rz * rz + 1e-12f;
    float iv = rsqrtf(dd);
    float dist = dd * iv;
    float h0 = rx * iv, h1 = ry * iv, h2 = rz * iv;

    float uu = fminf(dist * 0.2f, 1.0f);
    float fc = 0.5f * (__cosf(3.14159265358979323846f * uu) + 1.0f);

    float rb[8];
#pragma unroll
    for (int b = 0; b < 8; b++) {
        float cb = 0.5f + (float)b * (4.5f / 7.0f);
        float dl = dist - cb;
        rb[b] = __expf(-4.0f * dl * dl) * fc;
    }

    g_edata[p * 3 + 0] = make_float4(h0, h1, h2, rb[0]);
    g_edata[p * 3 + 1] = make_float4(rb[1], rb[2], rb[3], rb[4]);
    g_edata[p * 3 + 2] = make_float4(rb[5], rb[6], rb[7], 0.0f);
}

// ---------------------------------------------------------------------------
// FUSED kernel: persistent warps, DYNAMIC work-stealing over nodes;
// lane = channel. Edge loop: sequential CSR walk, j prefetched one ahead.
// Wrad pre-scaled by 1/16 (norm folded into w — all messages are w-linear).
// ---------------------------------------------------------------------------
#define NWARPS 4

__global__ __launch_bounds__(128, 3)
void fused_kernel(const float* __restrict__ Wrad,
                  const float* __restrict__ U,
                  const float* __restrict__ V,
                  const float* __restrict__ Wg,
                  float* __restrict__ out,
                  int N)
{
    extern __shared__ float sh[];
    float* sWm = sh;                           // 11*1024 pair-interleaved
    float* sWg = sWm + 11264;                  // 3*1024 pair-interleaved
    float* sX  = sWg + 3072;                   // NWARPS * 27 * 32
    float* sY  = sX + NWARPS * 27 * 32;        // NWARPS * 32

    // pair interleave: idx = m*1024 + (c>>1)*64 + d*2 + (c&1)
    for (int i = threadIdx.x; i < 11 * 1024; i += blockDim.x) {
        float v = (i < 3 * 1024) ? U[i] : V[i - 3 * 1024];
        int m = i >> 10, c = (i >> 5) & 31, d = i & 31;
        sWm[(m << 10) + ((c >> 1) << 6) + (d << 1) + (c & 1)] = v;
    }
    for (int i = threadIdx.x; i < 3 * 1024; i += blockDim.x) {
        int m = i >> 10, c = (i >> 5) & 31, d = i & 31;
        sWg[(m << 10) + ((c >> 1) << 6) + (d << 1) + (c & 1)] = Wg[i];
    }
    __syncthreads();

    int lane = threadIdx.x & 31;
    int warp = threadIdx.x >> 5;

    // Wrad[p][b][lane], packed over basis pairs, PRE-SCALED by 1/16
    const float norm = 1.0f / 16.0f;
    u64 Wreg2[44];
#pragma unroll
    for (int p = 0; p < 11; p++)
#pragma unroll
        for (int i = 0; i < 4; i++) {
            float lo = Wrad[(p * 8 + 2 * i) * 32 + lane] * norm;
            float hi = Wrad[(p * 8 + 2 * i + 1) * 32 + lane] * norm;
            PACK2(Wreg2[p * 4 + i], lo, hi);
        }

    int d = lane;
    const u64* wm64 = (const u64*)sWm;         // idx: m*512 + cp*32 + d
    const u64* wg64 = (const u64*)sWg;
    float* Xs = sX + warp * 27 * 32;
    float* Ys = sY + warp * 32;

    for (;;) {
        // dynamic node fetch (warp-uniform)
        int n;
        if (lane == 0) n = atomicAdd(&g_next, 1);
        n = __shfl_sync(0xffffffffu, n, 0);
        if (n >= N) break;

        // ================= EDGE PHASE =================
        float a0 = 0.0f;
        float a1[3] = {0.0f, 0.0f, 0.0f};
        float a2[9] = {0.0f, 0.0f, 0.0f, 0.0f, 0.0f, 0.0f, 0.0f, 0.0f, 0.0f};

        int beg = g_off[n];
        int end = g_off[n + 1];

        if (beg < end) {
            int jn = g_j[beg];                 // prefetch j for first edge
            for (int pos = beg; pos < end; pos++) {
                int j = jn;
                int nx = (pos + 1 < end) ? (pos + 1) : pos;
                jn = g_j[nx];

                int jc = j * 32 + lane;

                // packed channel gathers: 3x LDG.128 + 1x LDG.32
                float4 f0 = g_f0[jc];
                float4 fa = g_f2a[jc];
                float4 fb = g_f2b[jc];
                float  fcv = g_f2c[jc];

                // broadcast loads of CSR-ordered edge data
                float4 q0 = g_edata[pos * 3 + 0];
                float4 q1 = g_edata[pos * 3 + 1];
                float4 q2 = g_edata[pos * 3 + 2];

                float g0 = f0.x;
                float g1v[3] = { f0.y, f0.z, f0.w };
                float g2[9] = { fa.x, fa.y, fa.z, fa.w,
                                fb.x, fb.y, fb.z, fb.w, fcv };

                float h0 = q0.x, h1 = q0.y, h2 = q0.z;

                // basis values, packed over pairs
                u64 rb2[4];
                PACK2(rb2[0], q0.w, q1.x);
                PACK2(rb2[1], q1.y, q1.z);
                PACK2(rb2[2], q1.w, q2.x);
                PACK2(rb2[3], q2.y, q2.z);

                // w[p] = sum_b rb[b] * W[p,b]   (pre-normalized)
                float w[11];
#pragma unroll
                for (int p = 0; p < 11; p++) {
                    u64 acc = 0ull;
#pragma unroll
                    for (int i = 0; i < 4; i++) FMA2(acc, rb2[i], Wreg2[p * 4 + i], acc);
                    w[p] = hadd2(acc);
                }

                float hh[3] = {h0, h1, h2};
                float d1 = g1v[0] * h0 + g1v[1] * h1 + g1v[2] * h2;
                float d2[3];
#pragma unroll
                for (int a = 0; a < 3; a++)
                    d2[a] = g2[a * 3 + 0] * h0 + g2[a * 3 + 1] * h1 + g2[a * 3 + 2] * h2;
                float q = d2[0] * h0 + d2[1] * h1 + d2[2] * h2;

                a0 += g0 * w[0] + d1 * w[4] + q * w[9];

                float s01 = g0 * w[1] + d1 * w[6];
#pragma unroll
                for (int a = 0; a < 3; a++)
                    a1[a] += s01 * hh[a] + g1v[a] * w[3] + d2[a] * w[8];

                float gw2 = g0 * w[2];
#pragma unroll
                for (int a = 0; a < 3; a++) {
                    float pre = gw2 * hh[a] + g1v[a] * w[5] + d2[a] * w[10];
#pragma unroll
                    for (int b = 0; b < 3; b++)
                        a2[a * 3 + b] += pre * hh[b] + g2[a * 3 + b] * w[7];
                }
            }
        }

        // ================= NODE PHASE =================
        float s1 = a1[0] * a1[0] + a1[1] * a1[1] + a1[2] * a1[2];
        float s2 = 0.0f;
#pragma unroll
        for (int k = 0; k < 9; k++) s2 += a2[k] * a2[k];
        float t[3];
#pragma unroll
        for (int b = 0; b < 3; b++)
            t[b] = a1[0] * a2[0 * 3 + b] + a1[1] * a2[1 * 3 + b] + a1[2] * a2[2 * 3 + b];
        float r[9];
#pragma unroll
        for (int a = 0; a < 3; a++)
#pragma unroll
            for (int b = 0; b < 3; b++)
                r[a * 3 + b] = a2[a * 3 + 0] * a2[0 * 3 + b]
                             + a2[a * 3 + 1] * a2[1 * 3 + b]
                             + a2[a * 3 + 2] * a2[2 * 3 + b];

        Xs[0 * 32 + lane] = a0;
        Xs[1 * 32 + lane] = s1;
        Xs[2 * 32 + lane] = s2;
#pragma unroll
        for (int a = 0; a < 3; a++) { Xs[(3 + a) * 32 + lane] = a1[a]; Xs[(6 + a) * 32 + lane] = t[a]; }
#pragma unroll
        for (int k = 0; k < 9; k++) { Xs[(9 + k) * 32 + lane] = a2[k]; Xs[(18 + k) * 32 + lane] = r[k]; }
        __syncwarp();

        u64 y0acc = 0ull;
        u64 y1acc[3] = {0ull, 0ull, 0ull};
        u64 y2acc[9] = {0ull, 0ull, 0ull, 0ull, 0ull, 0ull, 0ull, 0ull, 0ull};

#pragma unroll 2
        for (int cp = 0; cp < 16; cp++) {
            int c = cp * 2;
            int wb = cp * 32 + d;

            u64 xa0p = *(const u64*)(Xs + 0 * 32 + c);
            u64 xs1p = *(const u64*)(Xs + 1 * 32 + c);
            u64 xs2p = *(const u64*)(Xs + 2 * 32 + c);

            FMA2(y0acc, xa0p, wm64[0 * 512 + wb], y0acc);
            u64 xa0sq; MUL2(xa0sq, xa0p, xa0p);
            FMA2(y0acc, xa0sq, wm64[3 * 512 + wb], y0acc);
            FMA2(y0acc, xs1p, wm64[6 * 512 + wb], y0acc);
            FMA2(y0acc, xs2p, wm64[9 * 512 + wb], y0acc);

            u64 wU1 = wm64[1 * 512 + wb];
            u64 wV1 = wm64[4 * 512 + wb];
            u64 wV5 = wm64[8 * 512 + wb];
            u64 xa1p[3];
#pragma unroll
            for (int a = 0; a < 3; a++) {
                xa1p[a] = *(const u64*)(Xs + (3 + a) * 32 + c);
                u64 xtp = *(const u64*)(Xs + (6 + a) * 32 + c);
                FMA2(y1acc[a], xa1p[a], wU1, y1acc[a]);
                u64 p01; MUL2(p01, xa0p, xa1p[a]);
                FMA2(y1acc[a], p01, wV1, y1acc[a]);
                FMA2(y1acc[a], xtp, wV5, y1acc[a]);
            }

            u64 wU2 = wm64[2 * 512 + wb];
            u64 wV2 = wm64[5 * 512 + wb];
            u64 wV4 = wm64[7 * 512 + wb];
            u64 wV7 = wm64[10 * 512 + wb];
#pragma unroll
            for (int a = 0; a < 3; a++) {
#pragma unroll
                for (int b = 0; b < 3; b++) {
                    int k = a * 3 + b;
                    u64 xa2p = *(const u64*)(Xs + (9 + k) * 32 + c);
                    u64 xrp  = *(const u64*)(Xs + (18 + k) * 32 + c);
                    FMA2(y2acc[k], xa2p, wU2, y2acc[k]);
                    u64 p02; MUL2(p02, xa0p, xa2p);
                    FMA2(y2acc[k], p02, wV2, y2acc[k]);
                    u64 p11; MUL2(p11, xa1p[a], xa1p[b]);
                    FMA2(y2acc[k], p11, wV4, y2acc[k]);
                    FMA2(y2acc[k], xrp, wV7, y2acc[k]);
                }
            }
        }

        float y0 = hadd2(y0acc);
        float y1[3], y2[9];
#pragma unroll
        for (int a = 0; a < 3; a++) y1[a] = hadd2(y1acc[a]);
#pragma unroll
        for (int k = 0; k < 9; k++) y2[k] = hadd2(y2acc[k]);

        // gates
        Ys[d] = y0;
        __syncwarp();
        u64 gp0a = 0ull, gp1a = 0ull, gp2a = 0ull;
#pragma unroll 4
        for (int cp = 0; cp < 16; cp++) {
            u64 yp = *(const u64*)(Ys + cp * 2);
            int wb = cp * 32 + d;
            FMA2(gp0a, yp, wg64[0 * 512 + wb], gp0a);
            FMA2(gp1a, yp, wg64[1 * 512 + wb], gp1a);
            FMA2(gp2a, yp, wg64[2 * 512 + wb], gp2a);
        }
        float gp0 = hadd2(gp0a), gp1 = hadd2(gp1a), gp2 = hadd2(gp2a);
        float gate0 = gp0 / (1.0f + __expf(-gp0));
        float gate1 = gp1 / (1.0f + __expf(-gp1));
        float gate2 = gp2 / (1.0f + __expf(-gp2));

        int i0 = n * 32 + lane;
        float* out0 = out;
        float* out1 = out + (size_t)N * 32;
        float* out2 = out + (size_t)N * 32 * 4;

        // residuals from packed features (4 wide loads)
        float4 f0 = g_f0[i0];
        float4 fa = g_f2a[i0];
        float4 fb = g_f2b[i0];
        float  fcv = g_f2c[i0];

        out0[i0] = f0.x + gate0;
        float* o1p = out1 + (size_t)i0 * 3;
        o1p[0] = f0.y + y1[0] * gate1;
        o1p[1] = f0.z + y1[1] * gate1;
        o1p[2] = f0.w + y1[2] * gate1;
        float* o2p = out2 + (size_t)i0 * 9;
        float n2v[9] = { fa.x, fa.y, fa.z, fa.w, fb.x, fb.y, fb.z, fb.w, fcv };
#pragma unroll
        for (int k = 0; k < 9; k++) o2p[k] = n2v[k] + y2[k] * gate2;
        __syncwarp();
    }
}

// ---------------------------------------------------------------------------
extern "C" void kernel_launch(void* const* d_in, const int* in_sizes, int n_in,
                              void* d_out, int out_size)
{
    const float* node0 = (const float*)d_in[0];
    const float* node1 = (const float*)d_in[1];
    const float* node2 = (const float*)d_in[2];
    const float* rij   = (const float*)d_in[3];
    const float* Wrad  = (const float*)d_in[4];
    const float* U     = (const float*)d_in[5];
    const float* V     = (const float*)d_in[6];
    const float* Wg    = (const float*)d_in[7];
    const int*   idx_i = (const int*)d_in[8];
    const int*   idx_j = (const int*)d_in[9];
    float* out = (float*)d_out;

    int N = in_sizes[0] / 32;
    int E = in_sizes[8];
    int NC = N * 32;
    int GMAX = (E > NC) ? E : NC;

    int fused_smem = (11264 + 3072 + NWARPS * 27 * 32 + NWARPS * 32) * (int)sizeof(float);
    cudaFuncSetAttribute(fused_kernel, cudaFuncAttributeMaxDynamicSharedMemorySize, fused_smem);

    // zero g_deg + work counter via memset nodes (not kernel launches)
    void* degPtr = nullptr;
    cudaGetSymbolAddress(&degPtr, g_deg);
    cudaMemsetAsync(degPtr, 0, (size_t)N * sizeof(int));
    void* nextPtr = nullptr;
    cudaGetSymbolAddress(&nextPtr, g_next);
    cudaMemsetAsync(nextPtr, 0, sizeof(int));

    hist_pack_kernel<<<(GMAX + 255) / 256, 256>>>(idx_i, node0, node1, node2, E, NC);
    scan_kernel<<<1, 1024>>>(N, E);
    scatter_pre_kernel<<<(E + 255) / 256, 256>>>(idx_i, idx_j, rij, E);
    fused_kernel<<<444, 128, fused_smem>>>(Wrad, U, V, Wg, out, N);
}